// round 15
// baseline (speedup 1.0000x reference)
#include <cuda_runtime.h>
#include <cuda_bf16.h>

#define NN 20000
#define DD 32
#define HH 64
#define GG 256
#define MT 48      // nodes per LSTM block
#define NSTR 50    // h-state node stride in u64 (400B rows; 16B-aligned)

typedef unsigned long long u64;
typedef unsigned int u32;

// ---------------- device scratch (no allocations allowed) ----------------
__device__ int   g_nbrs[NN * DD];
__device__ float g_bufA[NN * HH];
__device__ float g_bufB[NN * HH];
__device__ u64   g_projPK[NN * 128];  // packed proj: [node][jp*32+tg] = (gate[tg+64jp], gate[tg+64jp+32])
__device__ float g_agg [NN * HH];
__device__ u64   g_wPK [HH * 128];    // packed W_hh: [k][jp*32+tg] = (w[64jp+tg][k], w[64jp+tg+32][k])

__device__ __forceinline__ float tanhx(float x) {
    float y; asm("tanh.approx.f32 %0, %1;" : "=f"(y) : "f"(x)); return y;
}
__device__ __forceinline__ float sigmx(float x) {
    return fmaf(tanhx(0.5f * x), 0.5f, 0.5f);
}
__device__ __forceinline__ u64 pack2(float lo, float hi) {
    u64 r;
    asm("mov.b64 %0, {%1, %2};" : "=l"(r) : "r"(__float_as_uint(lo)), "r"(__float_as_uint(hi)));
    return r;
}
__device__ __forceinline__ void unpack2(u64 v, float& lo, float& hi) {
    u32 a, b;
    asm("mov.b64 {%0, %1}, %2;" : "=r"(a), "=r"(b) : "l"(v));
    lo = __uint_as_float(a); hi = __uint_as_float(b);
}
__device__ __forceinline__ u64 fma2(u64 a, u64 b, u64 c) {
    u64 d;
    asm("fma.rn.f32x2 %0, %1, %2, %3;" : "=l"(d) : "l"(a), "l"(b), "l"(c));
    return d;
}

// ---------------- sort neighbor rows (bitonic, registers) ----------------
__global__ void sort_kernel(const int* __restrict__ nbr) {
    int node = blockIdx.x * blockDim.x + threadIdx.x;
    if (node >= NN) return;
    int v[DD];
#pragma unroll
    for (int i = 0; i < DD; i++) v[i] = nbr[node * DD + i];
#pragma unroll
    for (int k = 2; k <= DD; k <<= 1)
#pragma unroll
        for (int j = k >> 1; j > 0; j >>= 1)
#pragma unroll
            for (int i = 0; i < DD; i++) {
                int l = i ^ j;
                if (l > i) {
                    int a = v[i], b = v[l];
                    if ((a > b) == ((i & k) == 0)) { v[i] = b; v[l] = a; }
                }
            }
#pragma unroll
    for (int i = 0; i < DD; i++) g_nbrs[node * DD + i] = v[i];
}

// ---------------- pack W_hh -> g_wPK[k][jp*32+tg] -------------------------
__global__ void packw_kernel(const float* __restrict__ W) {
    int k = blockIdx.x, g = threadIdx.x;        // g in [0,128)
    int jp = g >> 5, tg = g & 31;
    float w0 = W[(64 * jp + tg) * HH + k];
    float w1 = W[(64 * jp + tg + 32) * HH + k];
    g_wPK[k * 128 + g] = pack2(w0, w1);
}

// ---------------- proj: packed gates -> g_projPK  (32 nodes/block) --------
__global__ void proj_kernel(const float* __restrict__ x, int in_d,
                            const float* __restrict__ W_ih,
                            const float* __restrict__ b_ih,
                            const float* __restrict__ b_hh) {
    extern __shared__ float smf[];
    float* sW = smf;                 // [in_d][256] transposed
    float* sB = sW + in_d * GG;      // [256]
    float* sX = sB + GG;             // [32][in_d]
    int tid = threadIdx.x;
    for (int idx = tid; idx < in_d * GG; idx += 256) {
        int g = idx / in_d, k = idx - g * in_d;
        sW[k * GG + g] = W_ih[idx];
    }
    if (tid < GG) sB[tid] = b_ih[tid] + b_hh[tid];
    int node0 = blockIdx.x * 32;
    for (int idx = tid; idx < 32 * in_d; idx += 256) {
        int i = idx / in_d, k = idx - i * in_d;
        sX[idx] = x[(node0 + i) * in_d + k];
    }
    __syncthreads();
    int w = tid >> 5, tg = tid & 31;
    float acc[4][8];   // [node i][gate j]: gate = tg + 32*j
#pragma unroll
    for (int i = 0; i < 4; i++)
#pragma unroll
        for (int j = 0; j < 8; j++) acc[i][j] = sB[tg + 32 * j];
    for (int k = 0; k < in_d; k++) {
        float xv[4];
#pragma unroll
        for (int i = 0; i < 4; i++) xv[i] = sX[(w * 4 + i) * in_d + k];
#pragma unroll
        for (int j = 0; j < 8; j++) {
            float b = sW[k * GG + tg + 32 * j];
#pragma unroll
            for (int i = 0; i < 4; i++) acc[i][j] += xv[i] * b;
        }
    }
#pragma unroll
    for (int i = 0; i < 4; i++) {
        int node = node0 + w * 4 + i;
#pragma unroll
        for (int jp = 0; jp < 4; jp++)   // pair (gate tg+64jp, gate tg+64jp+32)
            g_projPK[(size_t)node * 128 + jp * 32 + tg] = pack2(acc[i][2 * jp], acc[i][2 * jp + 1]);
    }
}

// ---------------- LSTM recurrence (FFMA2, all operands pre-packed) --------
// 192 threads (6 warps) x 48 nodes; warp owns 8 nodes, syncs only itself.
// k-loop: 4 LDG.64 (weights) + 4 LDS.128 (dup'd h) + 32 fma2; zero packs.
__global__ __launch_bounds__(192, 3)
void lstm_kernel() {
    extern __shared__ u64 sH[];   // [2][64][NSTR] dup'd h pairs, 51.2 KB
    int tid = threadIdx.x;
    int tg = tid & 31, tn = tid >> 5;

    int node0 = blockIdx.x * MT + tn * 8;
    int base = tn * 8;
    float c0[8], c1[8];
#pragma unroll
    for (int i = 0; i < 8; i++) { c0[i] = 0.f; c1[i] = 0.f; }

    int p = 0;
#pragma unroll 1
    for (int t = 0; t < DD; t++) {
        u64 acc[4][8];   // [gate-pair jp][node i]; halves = hidden tg / tg+32
        // gather: packed proj of t-th sorted neighbor (4 LDG.64 per node)
#pragma unroll
        for (int i = 0; i < 8; i++) {
            int n = node0 + i;
            int nb = (n < NN) ? g_nbrs[n * DD + t] : 0;
            const u64* pr = g_projPK + (size_t)nb * 128 + tg;
#pragma unroll
            for (int jp = 0; jp < 4; jp++)
                acc[jp][i] = __ldg(&pr[jp * 32]);
        }
        if (t) {
            const u64* sHr = sH + p * (HH * NSTR) + base;
#pragma unroll 2
            for (int k = 0; k < HH; k++) {
                const u64* wk = g_wPK + k * 128 + tg;
                u64 b0 = __ldg(wk);
                u64 b1 = __ldg(wk + 32);
                u64 b2 = __ldg(wk + 64);
                u64 b3 = __ldg(wk + 96);
                const u64* hr = sHr + k * NSTR;
                ulonglong2 q0 = *(const ulonglong2*)(hr);      // dup'd h, nodes 0,1
                ulonglong2 q1 = *(const ulonglong2*)(hr + 2);  // nodes 2,3
                ulonglong2 q2 = *(const ulonglong2*)(hr + 4);  // nodes 4,5
                ulonglong2 q3 = *(const ulonglong2*)(hr + 6);  // nodes 6,7
                acc[0][0] = fma2(q0.x, b0, acc[0][0]); acc[1][0] = fma2(q0.x, b1, acc[1][0]);
                acc[2][0] = fma2(q0.x, b2, acc[2][0]); acc[3][0] = fma2(q0.x, b3, acc[3][0]);
                acc[0][1] = fma2(q0.y, b0, acc[0][1]); acc[1][1] = fma2(q0.y, b1, acc[1][1]);
                acc[2][1] = fma2(q0.y, b2, acc[2][1]); acc[3][1] = fma2(q0.y, b3, acc[3][1]);
                acc[0][2] = fma2(q1.x, b0, acc[0][2]); acc[1][2] = fma2(q1.x, b1, acc[1][2]);
                acc[2][2] = fma2(q1.x, b2, acc[2][2]); acc[3][2] = fma2(q1.x, b3, acc[3][2]);
                acc[0][3] = fma2(q1.y, b0, acc[0][3]); acc[1][3] = fma2(q1.y, b1, acc[1][3]);
                acc[2][3] = fma2(q1.y, b2, acc[2][3]); acc[3][3] = fma2(q1.y, b3, acc[3][3]);
                acc[0][4] = fma2(q2.x, b0, acc[0][4]); acc[1][4] = fma2(q2.x, b1, acc[1][4]);
                acc[2][4] = fma2(q2.x, b2, acc[2][4]); acc[3][4] = fma2(q2.x, b3, acc[3][4]);
                acc[0][5] = fma2(q2.y, b0, acc[0][5]); acc[1][5] = fma2(q2.y, b1, acc[1][5]);
                acc[2][5] = fma2(q2.y, b2, acc[2][5]); acc[3][5] = fma2(q2.y, b3, acc[3][5]);
                acc[0][6] = fma2(q3.x, b0, acc[0][6]); acc[1][6] = fma2(q3.x, b1, acc[1][6]);
                acc[2][6] = fma2(q3.x, b2, acc[2][6]); acc[3][6] = fma2(q3.x, b3, acc[3][6]);
                acc[0][7] = fma2(q3.y, b0, acc[0][7]); acc[1][7] = fma2(q3.y, b1, acc[1][7]);
                acc[2][7] = fma2(q3.y, b2, acc[2][7]); acc[3][7] = fma2(q3.y, b3, acc[3][7]);
            }
        }
        // cell update: acc[jp][i] halves = gate jp for hidden tg (lo), tg+32 (hi)
        u64* sHw = sH + (p ^ 1) * (HH * NSTR);
        bool last = (t == DD - 1);
#pragma unroll
        for (int m = 0; m < 4; m++) {
            int i0 = 2 * m, i1 = 2 * m + 1;
            float ia0, ia1, fa0, fa1, ga0, ga1, oa0, oa1;
            float ib0, ib1, fb0, fb1, gb0, gb1, ob0, ob1;
            unpack2(acc[0][i0], ia0, ia1); unpack2(acc[1][i0], fa0, fa1);
            unpack2(acc[2][i0], ga0, ga1); unpack2(acc[3][i0], oa0, oa1);
            unpack2(acc[0][i1], ib0, ib1); unpack2(acc[1][i1], fb0, fb1);
            unpack2(acc[2][i1], gb0, gb1); unpack2(acc[3][i1], ob0, ob1);
            c0[i0] = sigmx(fa0) * c0[i0] + sigmx(ia0) * tanhx(ga0);
            c1[i0] = sigmx(fa1) * c1[i0] + sigmx(ia1) * tanhx(ga1);
            float h0a = sigmx(oa0) * tanhx(c0[i0]);
            float h1a = sigmx(oa1) * tanhx(c1[i0]);
            c0[i1] = sigmx(fb0) * c0[i1] + sigmx(ib0) * tanhx(gb0);
            c1[i1] = sigmx(fb1) * c1[i1] + sigmx(ib1) * tanhx(gb1);
            float h0b = sigmx(ob0) * tanhx(c0[i1]);
            float h1b = sigmx(ob1) * tanhx(c1[i1]);
            if (!last) {
                // store duplicated pairs: row = source hidden index, col = node
                *(ulonglong2*)(sHw + tg * NSTR + base + 2 * m) =
                    make_ulonglong2(pack2(h0a, h0a), pack2(h0b, h0b));
                *(ulonglong2*)(sHw + (tg + 32) * NSTR + base + 2 * m) =
                    make_ulonglong2(pack2(h1a, h1a), pack2(h1b, h1b));
            } else {
                int na = node0 + i0, nb = na + 1;
                if (na < NN) {
                    g_agg[na * HH + tg]      = h0a;
                    g_agg[na * HH + tg + 32] = h1a;
                }
                if (nb < NN) {
                    g_agg[nb * HH + tg]      = h0b;
                    g_agg[nb * HH + tg + 32] = h1b;
                }
            }
        }
        __syncwarp();
        p ^= 1;
    }
}

// ---------------- h_next = relu([x, agg] @ Wl^T + bl)  (32 nodes/block) ---
__global__ void combine_kernel(const float* __restrict__ x, int in_d,
                               const float* __restrict__ Wl,
                               const float* __restrict__ bl,
                               float* __restrict__ out) {
    extern __shared__ float smf[];
    int C = in_d + HH;
    float* sW = smf;           // [C][64] transposed
    float* sB = sW + C * HH;   // [64]
    float* sX = sB + HH;       // [32][C]
    int tid = threadIdx.x;
    for (int idx = tid; idx < C * HH; idx += 256) {
        int o = idx / C, k = idx - o * C;
        sW[k * HH + o] = Wl[idx];
    }
    if (tid < HH) sB[tid] = bl[tid];
    int node0 = blockIdx.x * 32;
    for (int idx = tid; idx < 32 * C; idx += 256) {
        int i = idx / C, k = idx - i * C;
        sX[idx] = (k < in_d) ? x[(node0 + i) * in_d + k]
                             : g_agg[(node0 + i) * HH + (k - in_d)];
    }
    __syncthreads();
    int w = tid >> 5, tg = tid & 31;
    u64 acc[4];
#pragma unroll
    for (int i = 0; i < 4; i++) acc[i] = *(const u64*)(sB + 2 * tg);
    for (int k = 0; k < C; k++) {
        u64 wp = *(const u64*)(sW + k * HH + 2 * tg);
#pragma unroll
        for (int i = 0; i < 4; i++) {
            float xv = sX[(w * 4 + i) * C + k];
            acc[i] = fma2(pack2(xv, xv), wp, acc[i]);
        }
    }
#pragma unroll
    for (int i = 0; i < 4; i++) {
        float a0, a1;
        unpack2(acc[i], a0, a1);
        int node = node0 + w * 4 + i;
        *(float2*)(out + node * HH + 2 * tg) = make_float2(fmaxf(a0, 0.f), fmaxf(a1, 0.f));
    }
}

// ---------------- out = h @ W_out^T + b_out -------------------------------
__global__ void out_kernel(const float* __restrict__ h,
                           const float* __restrict__ W_out,
                           const float* __restrict__ b_out,
                           float* __restrict__ out) {
    int tid = threadIdx.x;
    int node = blockIdx.x * 8 + (tid >> 5);
    int tg = tid & 31;
    float a = h[node * HH + tg] * W_out[tg] + h[node * HH + tg + 32] * W_out[tg + 32];
#pragma unroll
    for (int s = 16; s > 0; s >>= 1) a += __shfl_down_sync(0xffffffffu, a, s);
    if (tg == 0) out[node] = a + b_out[0];
}

// ---------------- launcher ------------------------------------------------
extern "C" void kernel_launch(void* const* d_in, const int* in_sizes, int n_in,
                              void* d_out, int out_size) {
    const float* node_features = (const float*)d_in[0];
    const int*   nbr           = (const int*)d_in[1];
    const float *W_ih[3], *W_hh[3], *b_ih[3], *b_hh[3], *Wl[3], *bl[3];
    for (int l = 0; l < 3; l++) {
        W_ih[l] = (const float*)d_in[2 + 6 * l + 0];
        W_hh[l] = (const float*)d_in[2 + 6 * l + 1];
        b_ih[l] = (const float*)d_in[2 + 6 * l + 2];
        b_hh[l] = (const float*)d_in[2 + 6 * l + 3];
        Wl[l]   = (const float*)d_in[2 + 6 * l + 4];
        bl[l]   = (const float*)d_in[2 + 6 * l + 5];
    }
    const float* W_out = (const float*)d_in[20];
    const float* b_out = (const float*)d_in[21];
    float* out = (float*)d_out;

    float *bufA, *bufB;
    cudaGetSymbolAddress((void**)&bufA, g_bufA);
    cudaGetSymbolAddress((void**)&bufB, g_bufB);

    size_t lstm_sm = (size_t)2 * HH * NSTR * 8;   // 51.2 KB
    cudaFuncSetAttribute(proj_kernel, cudaFuncAttributeMaxDynamicSharedMemorySize, 80000);
    cudaFuncSetAttribute(lstm_kernel, cudaFuncAttributeMaxDynamicSharedMemorySize, (int)lstm_sm);
    cudaFuncSetAttribute(combine_kernel, cudaFuncAttributeMaxDynamicSharedMemorySize, 56000);

    sort_kernel<<<(NN + 255) / 256, 256>>>(nbr);

    const float* x = node_features;
    float* nxt = bufA;
    int grid_lstm = (NN + MT - 1) / MT;   // 417
    for (int l = 0; l < 3; l++) {
        int in_d = (l == 0) ? 3 : 64;
        size_t proj_sm = (size_t)(in_d * GG + GG + 32 * in_d) * 4;
        packw_kernel<<<HH, 128>>>(W_hh[l]);
        proj_kernel<<<NN / 32, 256, proj_sm>>>(x, in_d, W_ih[l], b_ih[l], b_hh[l]);
        lstm_kernel<<<grid_lstm, 192, lstm_sm>>>();
        int C = in_d + HH;
        size_t comb_sm = (size_t)(C * HH + HH + 32 * C) * 4;
        combine_kernel<<<NN / 32, 256, comb_sm>>>(x, in_d, Wl[l], bl[l], nxt);
        x = nxt;
        nxt = (nxt == bufA) ? bufB : bufA;
    }
    out_kernel<<<NN / 8, 256>>>(x, W_out, b_out, out);
}